// round 9
// baseline (speedup 1.0000x reference)
#include <cuda_runtime.h>
#include <cuda_bf16.h>
#include <cstdint>

// Problem constants (shapes fixed by dataset)
#define BB   16      // batch
#define CC   32      // channels in added; original has CC+1
#define HH   256     // grid H = W
#define TT   20      // boxes per batch
#define CELLS (HH*HH)
#define GPB   (CELLS/4)     // 4-cell groups per batch (= uint4 idx in a plane)
#define VOX  0.8f
#define INVVOX 1.25f

#define C_BLOCKS 512         // consumer blocks
#define C_THREADS 256
#define NWARPS  (C_BLOCKS * (C_THREADS/32))   // 4096 grid-stride warps

// Persistent scratch (no cudaMalloc). Static zero-init; every consumer
// resets what it reads so graph replays start clean.
__device__ unsigned int g_mask[BB * GPB];        // 4 mask bits per group
__device__ unsigned int g_wlist[BB * GPB];       // packed (b<<14)|group
__device__ unsigned int g_wcount;
__device__ unsigned int g_inter[BB];
__device__ unsigned int g_union[BB];
__device__ unsigned int g_ticket;

// ---------------------------------------------------------------------------
// K1: rasterize boxes; claim groups via atomicOr; first-claimer appends the
// group to the worklist (warp-aggregated atomicAdd).
// ---------------------------------------------------------------------------
__global__ void __launch_bounds__(128)
k_rasterize(const float* __restrict__ boxes) {
    const int bt = blockIdx.x;            // 0 .. B*T-1
    const int b  = bt / TT;
    const float* bx = boxes + (size_t)bt * 7;

    const float cx = bx[0], cy = bx[1], cz = bx[2];
    const float dx = bx[3], dy = bx[4], dz = bx[5], yaw = bx[6];

    // z test constant per box: |0.8 - cz| <= dz/2 (reference uses <=)
    if (fabsf(VOX - cz) > 0.5f * dz) return;

    const float c  = cosf(yaw), s = sinf(yaw);
    const float hx = 0.5f * dx, hy = 0.5f * dy;

    // rotated-box AABB (meters), +1 cell safety margin
    const float ax = hx * fabsf(c) + hy * fabsf(s);
    const float ay = hx * fabsf(s) + hy * fabsf(c);
    const int i0 = max(0,      (int)floorf((cx - ax) * INVVOX) - 1);
    const int i1 = min(HH - 1, (int)ceilf ((cx + ax) * INVVOX) + 1);
    const int j0 = max(0,      (int)floorf((cy - ay) * INVVOX) - 1);
    const int j1 = min(HH - 1, (int)ceilf ((cy + ay) * INVVOX) + 1);
    const int ni = i1 - i0 + 1, nj = j1 - j0 + 1;
    const int n  = ni * nj;

    const int lane = threadIdx.x & 31;
    unsigned int* mask = g_mask + (size_t)b * GPB;

    // warp-uniform trip count: all lanes iterate while the warp base < n
    for (int k = threadIdx.x; (k - lane) < n; k += blockDim.x) {
        bool append = false;
        unsigned int ent = 0u;
        if (k < n) {
            const int i = i0 + k / nj;
            const int j = j0 + k % nj;
            const float px = (float)i * VOX - cx;
            const float py = (float)j * VOX - cy;
            const float rx = fmaf(py, s,  px * c);      //  px*c + py*s
            const float ry = fmaf(py, c, -px * s);      // -px*s + py*c
            if (fabsf(rx) < hx && fabsf(ry) < hy) {
                const int cell = i * HH + j;
                const int grp  = cell >> 2;
                const unsigned int bit = 1u << (cell & 3);
                const unsigned int old = atomicOr(&mask[grp], bit);
                if (old == 0u) {                         // first claim of group
                    append = true;
                    ent = ((unsigned)b << 14) | (unsigned)grp;
                }
            }
        }
        // warp-aggregated worklist append
        const unsigned int bal = __ballot_sync(0xFFFFFFFFu, append);
        if (bal) {
            const int cnt = __popc(bal);
            unsigned int base = 0u;
            if (lane == 0) base = atomicAdd(&g_wcount, (unsigned)cnt);
            base = __shfl_sync(0xFFFFFFFFu, base, 0);
            if (append)
                g_wlist[base + __popc(bal & ((1u << lane) - 1u))] = ent;
        }
    }
}

// ---------------------------------------------------------------------------
// K2: consume worklist. One entry per warp iteration; lane = channel.
// Two dense loads/entry (MLP=32 by construction), component-wise reduce-or.
// Self-cleans mask/count/counters; last block finalizes the scalar.
// ---------------------------------------------------------------------------
__global__ void __launch_bounds__(C_THREADS)
k_consume(const float* __restrict__ added,
          const float* __restrict__ orig,
          float* __restrict__ out) {
    const int lane = threadIdx.x & 31;
    const int wid  = threadIdx.x >> 5;
    const int gw   = blockIdx.x * (C_THREADS / 32) + wid;   // global warp id

    __shared__ unsigned int s_i[BB], s_u[BB];
    if (threadIdx.x < BB) { s_i[threadIdx.x] = 0u; s_u[threadIdx.x] = 0u; }
    __syncthreads();

    const unsigned int nw = g_wcount;
    const uint4* a4 = (const uint4*)added;
    const uint4* o4 = (const uint4*)orig;

    for (unsigned int e = gw; e < nw; e += NWARPS) {
        const unsigned int ent = g_wlist[e];
        const int grp = ent & 0x3FFFu;
        const int b   = ent >> 14;

        // lane ch covers channel `lane` of both tensors for this 4-cell group
        const uint4 va = a4[((size_t)b * CC + lane)           * GPB + grp];
        const uint4 vo = o4[((size_t)b * (CC + 1) + 1 + lane) * GPB + grp];

        const unsigned int ax = __reduce_or_sync(0xFFFFFFFFu, va.x);
        const unsigned int ay = __reduce_or_sync(0xFFFFFFFFu, va.y);
        const unsigned int az = __reduce_or_sync(0xFFFFFFFFu, va.z);
        const unsigned int aw = __reduce_or_sync(0xFFFFFFFFu, va.w);
        const unsigned int ox = __reduce_or_sync(0xFFFFFFFFu, vo.x);
        const unsigned int oy = __reduce_or_sync(0xFFFFFFFFu, vo.y);
        const unsigned int oz = __reduce_or_sync(0xFFFFFFFFu, vo.z);
        const unsigned int ow = __reduce_or_sync(0xFFFFFFFFu, vo.w);

        if (lane == 0) {
            const int midx = b * GPB + grp;
            const unsigned int mw = g_mask[midx];
            g_mask[midx] = 0u;                       // self-clean for replay
            const unsigned int av[4] = {ax, ay, az, aw};
            const unsigned int ov[4] = {ox, oy, oz, ow};
            unsigned int inter = 0u, uni = 0u;
            #pragma unroll
            for (int k = 0; k < 4; k++) {
                const bool m = (mw >> k) & 1u;
                const bool p = m && (av[k] != 0u);   // sum!=0 <=> any bit (nonneg)
                const bool o = m && (ov[k] != 0u);
                inter += (unsigned)(p && o);
                uni   += (unsigned)(p || o);
            }
            if (inter) atomicAdd(&s_i[b], inter);
            if (uni)   atomicAdd(&s_u[b], uni);
        }
    }
    __syncthreads();

    // flush block accumulators to global
    if (threadIdx.x < BB) {
        const unsigned int vi = s_i[threadIdx.x];
        const unsigned int vu = s_u[threadIdx.x];
        if (vi) atomicAdd(&g_inter[threadIdx.x], vi);
        if (vu) atomicAdd(&g_union[threadIdx.x], vu);
    }

    // ---- last-block finalization (+ scratch reset for next replay) --------
    __shared__ unsigned int s_last;
    if (threadIdx.x == 0) {
        __threadfence();
        s_last = (atomicAdd(&g_ticket, 1u) == (unsigned)(C_BLOCKS - 1)) ? 1u : 0u;
    }
    __syncthreads();
    if (s_last && wid == 0) {
        float iou = 0.0f;
        if (lane < BB) {
            const unsigned int ai = g_inter[lane];
            const unsigned int au = g_union[lane];
            g_inter[lane] = 0u;                      // reset for next replay
            g_union[lane] = 0u;
            iou = (float)ai / fmaxf((float)au, 1.0f);
        }
        #pragma unroll
        for (int off = 16; off > 0; off >>= 1)
            iou += __shfl_xor_sync(0xFFFFFFFFu, iou, off);
        if (lane == 0) {
            out[0] = (float)TT * iou / (float)BB;
            g_wcount = 0u;                           // reset worklist
            __threadfence();
            g_ticket = 0u;                           // reset ticket
        }
    }
}

// ---------------------------------------------------------------------------
extern "C" void kernel_launch(void* const* d_in, const int* in_sizes, int n_in,
                              void* d_out, int out_size) {
    const float* added = (const float*)d_in[0];   // (16,32,256,256)
    const float* orig  = (const float*)d_in[1];   // (16,33,256,256)
    const float* boxes = (const float*)d_in[2];   // (16,20,7)
    (void)in_sizes; (void)n_in; (void)out_size;   // tf_ego unused

    k_rasterize<<<BB * TT, 128>>>(boxes);
    k_consume<<<C_BLOCKS, C_THREADS>>>(added, orig, (float*)d_out);
}

// round 11
// speedup vs baseline: 1.4400x; 1.4400x over previous
#include <cuda_runtime.h>
#include <cuda_bf16.h>
#include <cstdint>

// Problem constants (shapes fixed by dataset)
#define BB   16      // batch
#define CC   32      // channels in added; original has CC+1
#define HH   256     // grid H = W
#define TT   20      // boxes per batch
#define CELLS (HH*HH)
#define SEGS  (CELLS/32)     // 32-cell row segments per batch = 2048
#define VOX  0.8f
#define INVVOX 1.25f

#define C_BLOCKS 256         // consumer blocks
#define C_THREADS 256
#define NWARPS  (C_BLOCKS * (C_THREADS/32))   // 2048 grid-stride warps

// Persistent scratch (no cudaMalloc). Static zero-init; consumers reset what
// they read so graph replays start clean.
__device__ unsigned int g_segmask[BB * SEGS];    // bit per cell in segment
__device__ unsigned int g_wlist[BB * SEGS];      // packed (b<<11)|seg
__device__ unsigned int g_wcount;
__device__ unsigned int g_inter[BB];
__device__ unsigned int g_union[BB];
__device__ unsigned int g_ticket;

// ---------------------------------------------------------------------------
// K1: rasterize boxes; claim 32-cell segments via atomicOr; first claimer
// appends the segment to the worklist (warp-aggregated).
// ---------------------------------------------------------------------------
__global__ void __launch_bounds__(128)
k_rasterize(const float* __restrict__ boxes) {
    const int bt = blockIdx.x;            // 0 .. B*T-1
    const int b  = bt / TT;
    const float* bx = boxes + (size_t)bt * 7;

    const float cx = bx[0], cy = bx[1], cz = bx[2];
    const float dx = bx[3], dy = bx[4], dz = bx[5], yaw = bx[6];

    // z test constant per box: |0.8 - cz| <= dz/2 (reference uses <=)
    if (fabsf(VOX - cz) > 0.5f * dz) return;

    const float c  = cosf(yaw), s = sinf(yaw);
    const float hx = 0.5f * dx, hy = 0.5f * dy;

    // rotated-box AABB (meters), +1 cell safety margin
    const float ax = hx * fabsf(c) + hy * fabsf(s);
    const float ay = hx * fabsf(s) + hy * fabsf(c);
    const int i0 = max(0,      (int)floorf((cx - ax) * INVVOX) - 1);
    const int i1 = min(HH - 1, (int)ceilf ((cx + ax) * INVVOX) + 1);
    const int j0 = max(0,      (int)floorf((cy - ay) * INVVOX) - 1);
    const int j1 = min(HH - 1, (int)ceilf ((cy + ay) * INVVOX) + 1);
    const int ni = i1 - i0 + 1, nj = j1 - j0 + 1;
    const int n  = ni * nj;

    const int lane = threadIdx.x & 31;
    unsigned int* segmask = g_segmask + (size_t)b * SEGS;

    // warp-uniform trip count so ballots are safe
    for (int k = threadIdx.x; (k - lane) < n; k += blockDim.x) {
        bool append = false;
        unsigned int ent = 0u;
        if (k < n) {
            const int i = i0 + k / nj;
            const int j = j0 + k % nj;
            const float px = (float)i * VOX - cx;
            const float py = (float)j * VOX - cy;
            const float rx = fmaf(py, s,  px * c);      //  px*c + py*s
            const float ry = fmaf(py, c, -px * s);      // -px*s + py*c
            if (fabsf(rx) < hx && fabsf(ry) < hy) {
                const int cell = i * HH + j;
                const int seg  = cell >> 5;
                const unsigned int bit = 1u << (cell & 31);
                const unsigned int old = atomicOr(&segmask[seg], bit);
                if (old == 0u) {                        // first claim
                    append = true;
                    ent = ((unsigned)b << 11) | (unsigned)seg;
                }
            }
        }
        const unsigned int bal = __ballot_sync(0xFFFFFFFFu, append);
        if (bal) {
            unsigned int base = 0u;
            if (lane == 0) base = atomicAdd(&g_wcount, (unsigned)__popc(bal));
            base = __shfl_sync(0xFFFFFFFFu, base, 0);
            if (append)
                g_wlist[base + __popc(bal & ((1u << lane) - 1u))] = ent;
        }
    }
}

// ---------------------------------------------------------------------------
// K2: consume worklist. One 32-cell segment per warp iteration; lane = cell.
// Every channel load is one fully-coalesced 128B line. 64 independent loads
// OR-accumulate into per-lane registers; ballots at the end.
// Self-cleans all scratch; last block finalizes the scalar.
// ---------------------------------------------------------------------------
__global__ void __launch_bounds__(C_THREADS)
k_consume(const float* __restrict__ added,
          const float* __restrict__ orig,
          float* __restrict__ out) {
    const int lane = threadIdx.x & 31;
    const int wid  = threadIdx.x >> 5;
    const int gw   = blockIdx.x * (C_THREADS / 32) + wid;   // global warp id

    __shared__ unsigned int s_i[BB], s_u[BB];
    if (threadIdx.x < BB) { s_i[threadIdx.x] = 0u; s_u[threadIdx.x] = 0u; }
    __syncthreads();

    const unsigned int nw = g_wcount;
    const unsigned int* au = (const unsigned int*)added;
    const unsigned int* ou = (const unsigned int*)orig;

    for (unsigned int e = gw; e < nw; e += NWARPS) {
        const unsigned int ent = g_wlist[e];
        const int seg = ent & (SEGS - 1);
        const int b   = ent >> 11;
        const int idx = seg * 32 + lane;              // cell index in plane

        const unsigned int* ap = au + ((size_t)b * CC)         * CELLS + idx;
        const unsigned int* op = ou + ((size_t)b * (CC+1) + 1) * CELLS + idx;

        unsigned int pa = 0u, po = 0u;                // per-cell OR over channels
        #pragma unroll
        for (int ch = 0; ch < CC; ch++) {
            pa |= __ldg(ap + (size_t)ch * CELLS);
            po |= __ldg(op + (size_t)ch * CELLS);
        }

        const unsigned int mw = g_segmask[b * SEGS + seg];
        if (lane == 0) g_segmask[b * SEGS + seg] = 0u;   // self-clean

        const bool m = (mw >> lane) & 1u;
        const bool p = m && (pa != 0u);               // sum!=0 <=> any bit (nonneg)
        const bool o = m && (po != 0u);
        const unsigned int bi = __ballot_sync(0xFFFFFFFFu, p && o);
        const unsigned int bu = __ballot_sync(0xFFFFFFFFu, p || o);
        if (lane == 0) {
            if (bi) atomicAdd(&s_i[b], (unsigned)__popc(bi));
            if (bu) atomicAdd(&s_u[b], (unsigned)__popc(bu));
        }
    }
    __syncthreads();

    // flush block accumulators to global
    if (threadIdx.x < BB) {
        const unsigned int vi = s_i[threadIdx.x];
        const unsigned int vu = s_u[threadIdx.x];
        if (vi) atomicAdd(&g_inter[threadIdx.x], vi);
        if (vu) atomicAdd(&g_union[threadIdx.x], vu);
    }

    // ---- last-block finalization (+ scratch reset for next replay) --------
    __shared__ unsigned int s_last;
    if (threadIdx.x == 0) {
        __threadfence();
        s_last = (atomicAdd(&g_ticket, 1u) == (unsigned)(C_BLOCKS - 1)) ? 1u : 0u;
    }
    __syncthreads();
    if (s_last && wid == 0) {
        float iou = 0.0f;
        if (lane < BB) {
            const unsigned int ai = g_inter[lane];
            const unsigned int au2 = g_union[lane];
            g_inter[lane] = 0u;                      // reset for next replay
            g_union[lane] = 0u;
            iou = (float)ai / fmaxf((float)au2, 1.0f);
        }
        #pragma unroll
        for (int off = 16; off > 0; off >>= 1)
            iou += __shfl_xor_sync(0xFFFFFFFFu, iou, off);
        if (lane == 0) {
            out[0] = (float)TT * iou / (float)BB;
            g_wcount = 0u;                           // reset worklist count
            __threadfence();
            g_ticket = 0u;                           // reset ticket
        }
    }
}

// ---------------------------------------------------------------------------
extern "C" void kernel_launch(void* const* d_in, const int* in_sizes, int n_in,
                              void* d_out, int out_size) {
    const float* added = (const float*)d_in[0];   // (16,32,256,256)
    const float* orig  = (const float*)d_in[1];   // (16,33,256,256)
    const float* boxes = (const float*)d_in[2];   // (16,20,7)
    (void)in_sizes; (void)n_in; (void)out_size;   // tf_ego unused

    k_rasterize<<<BB * TT, 128>>>(boxes);
    k_consume<<<C_BLOCKS, C_THREADS>>>(added, orig, (float*)d_out);
}